// round 6
// baseline (speedup 1.0000x reference)
#include <cuda_runtime.h>
#include <cuda_bf16.h>
#include <math.h>
#include <cstdint>

// Problem constants
#define BB 2
#define TT 2048
#define CC 2048
#define HH 16
#define HKV 8
#define DD 128
#define NROW (BB*TT)          // 4096

// ---------------- scratch (device globals; no allocation allowed) ----------
__device__ float g_q[(size_t)NROW * CC];
__device__ float g_kv[(size_t)NROW * CC];      // cols 0..1023 = k, 1024..2047 = v

__device__ __align__(16) __nv_bfloat16 g_xhi[(size_t)NROW * CC];
__device__ __align__(16) __nv_bfloat16 g_xlo[(size_t)NROW * CC];
__device__ __align__(16) __nv_bfloat16 g_ohi[(size_t)NROW * CC];
__device__ __align__(16) __nv_bfloat16 g_olo[(size_t)NROW * CC];
__device__ __align__(16) __nv_bfloat16 g_wqh[(size_t)CC * CC];
__device__ __align__(16) __nv_bfloat16 g_wql[(size_t)CC * CC];
__device__ __align__(16) __nv_bfloat16 g_wph[(size_t)CC * CC];
__device__ __align__(16) __nv_bfloat16 g_wpl[(size_t)CC * CC];
__device__ __align__(16) __nv_bfloat16 g_wkvh[(size_t)CC * CC];   // rows 0..1023 Wk^T, 1024..2047 Wv^T
__device__ __align__(16) __nv_bfloat16 g_wkvl[(size_t)CC * CC];

// head-major bf16 hi/lo Q/K/V for attention
__device__ __align__(16) __nv_bfloat16 g_qh[(size_t)BB * HH * TT * DD];
__device__ __align__(16) __nv_bfloat16 g_ql[(size_t)BB * HH * TT * DD];
__device__ __align__(16) __nv_bfloat16 g_kh[(size_t)BB * HKV * TT * DD];
__device__ __align__(16) __nv_bfloat16 g_kl[(size_t)BB * HKV * TT * DD];
__device__ __align__(16) __nv_bfloat16 g_vh[(size_t)BB * HKV * TT * DD];
__device__ __align__(16) __nv_bfloat16 g_vl[(size_t)BB * HKV * TT * DD];

// ======================= low-level helpers ==================================
__device__ __forceinline__ uint32_t smem_u32(const void* p) {
    uint32_t a;
    asm("{ .reg .u64 t; cvta.to.shared.u64 t, %1; cvt.u32.u64 %0, t; }"
        : "=r"(a) : "l"(p));
    return a;
}
__device__ __forceinline__ void ldsm4(uint32_t* r, uint32_t addr) {
    asm volatile("ldmatrix.sync.aligned.m8n8.x4.shared.b16 {%0,%1,%2,%3}, [%4];"
        : "=r"(r[0]), "=r"(r[1]), "=r"(r[2]), "=r"(r[3]) : "r"(addr));
}
__device__ __forceinline__ void ldsm4t(uint32_t* r, uint32_t addr) {
    asm volatile("ldmatrix.sync.aligned.m8n8.x4.trans.shared.b16 {%0,%1,%2,%3}, [%4];"
        : "=r"(r[0]), "=r"(r[1]), "=r"(r[2]), "=r"(r[3]) : "r"(addr));
}
__device__ __forceinline__ void mma_bf16(float* d, const uint32_t* a, const uint32_t* b) {
    asm volatile(
        "mma.sync.aligned.m16n8k16.row.col.f32.bf16.bf16.f32 "
        "{%0,%1,%2,%3}, {%4,%5,%6,%7}, {%8,%9}, {%0,%1,%2,%3};"
        : "+f"(d[0]), "+f"(d[1]), "+f"(d[2]), "+f"(d[3])
        : "r"(a[0]), "r"(a[1]), "r"(a[2]), "r"(a[3]), "r"(b[0]), "r"(b[1]));
}
__device__ __forceinline__ void cp_async16(uint32_t dst, const void* src) {
    asm volatile("cp.async.cg.shared.global [%0], [%1], 16;\n" :: "r"(dst), "l"(src));
}
#define CP_COMMIT() asm volatile("cp.async.commit_group;\n" ::: "memory")
#define CP_WAIT1()  asm volatile("cp.async.wait_group 1;\n" ::: "memory")
#define CP_WAIT0()  asm volatile("cp.async.wait_group 0;\n" ::: "memory")

__device__ __forceinline__ __nv_bfloat162 bfpair(float a, float b) {
    __nv_bfloat162 r; r.x = __float2bfloat16(a); r.y = __float2bfloat16(b); return r;
}
__device__ __forceinline__ void packsplit(float a, float b, uint32_t& hi, uint32_t& lo) {
    __nv_bfloat16 ha = __float2bfloat16(a), hb = __float2bfloat16(b);
    __nv_bfloat162 H; H.x = ha; H.y = hb;
    __nv_bfloat162 L;
    L.x = __float2bfloat16(a - __bfloat162float(ha));
    L.y = __float2bfloat16(b - __bfloat162float(hb));
    hi = *(uint32_t*)&H; lo = *(uint32_t*)&L;
}

// ======================= conversion kernels =================================
__global__ void split_kernel(const float4* __restrict__ in,
                             __nv_bfloat162* __restrict__ hi,
                             __nv_bfloat162* __restrict__ lo, int n4)
{
    int i = blockIdx.x * blockDim.x + threadIdx.x;
    if (i >= n4) return;
    float4 v = in[i];
    __nv_bfloat16 h0 = __float2bfloat16(v.x);
    __nv_bfloat16 h1 = __float2bfloat16(v.y);
    __nv_bfloat16 h2 = __float2bfloat16(v.z);
    __nv_bfloat16 h3 = __float2bfloat16(v.w);
    __nv_bfloat162 ph0; ph0.x = h0; ph0.y = h1;
    __nv_bfloat162 ph1; ph1.x = h2; ph1.y = h3;
    hi[2*i]   = ph0;
    hi[2*i+1] = ph1;
    __nv_bfloat162 pl0, pl1;
    pl0.x = __float2bfloat16(v.x - __bfloat162float(h0));
    pl0.y = __float2bfloat16(v.y - __bfloat162float(h1));
    pl1.x = __float2bfloat16(v.z - __bfloat162float(h2));
    pl1.y = __float2bfloat16(v.w - __bfloat162float(h3));
    lo[2*i]   = pl0;
    lo[2*i+1] = pl1;
}

// W: [K, N] row-major -> T{hi,lo}: [N, K] row-major (bf16 hi/lo split)
__global__ void transpose_split_kernel(const float* __restrict__ W,
                                       __nv_bfloat16* __restrict__ Thi,
                                       __nv_bfloat16* __restrict__ Tlo,
                                       int K, int N)
{
    __shared__ float t[32][33];
    int n0 = blockIdx.x * 32, k0 = blockIdx.y * 32;
    int tx = threadIdx.x, ty = threadIdx.y;   // (32, 8)
    #pragma unroll
    for (int j = 0; j < 32; j += 8)
        t[ty + j][tx] = W[(size_t)(k0 + ty + j) * N + n0 + tx];
    __syncthreads();
    #pragma unroll
    for (int j = 0; j < 32; j += 8) {
        float v = t[tx][ty + j];
        __nv_bfloat16 h = __float2bfloat16(v);
        __nv_bfloat16 l = __float2bfloat16(v - __bfloat162float(h));
        size_t oidx = (size_t)(n0 + ty + j) * K + k0 + tx;
        Thi[oidx] = h;
        Tlo[oidx] = l;
    }
}

// RoPE + bf16 hi/lo split + relayout [b,t,h,d] -> [b,h,t,d]; rs = input row stride
__global__ void rope_split_kernel(const float* __restrict__ in,
                                  __nv_bfloat16* __restrict__ oh,
                                  __nv_bfloat16* __restrict__ ol,
                                  int n_heads, int rs, int total)
{
    int idx = blockIdx.x * blockDim.x + threadIdx.x;
    if (idx >= total) return;
    int j = idx & 63;
    int h = (idx >> 6) % n_heads;
    int r = idx / (64 * n_heads);
    int b = r >> 11;
    int t = r & (TT - 1);

    float e = (float)(2 * j) * (1.0f / 128.0f);
    float inv = 1.0f / powf(10000.0f, e);
    float f = (float)t * inv;
    float c = cosf(f), s = sinf(f);

    const float* p = in + (size_t)r * rs + h * DD;
    float x1 = p[j], x2 = p[j + 64];
    float y1 = x1 * c - x2 * s;
    float y2 = x2 * c + x1 * s;

    size_t ob = ((size_t)(b * n_heads + h) * TT + t) * DD + j;
    __nv_bfloat16 h1 = __float2bfloat16(y1);
    __nv_bfloat16 h2 = __float2bfloat16(y2);
    oh[ob]      = h1;
    oh[ob + 64] = h2;
    ol[ob]      = __float2bfloat16(y1 - __bfloat162float(h1));
    ol[ob + 64] = __float2bfloat16(y2 - __bfloat162float(h2));
}

// V: bf16 hi/lo split + relayout [b,t,hk,d] -> [b,hk,t,d]; rs = input row stride
__global__ void v_split_kernel(const float* __restrict__ in,
                               __nv_bfloat16* __restrict__ oh,
                               __nv_bfloat16* __restrict__ ol, int rs, int total4)
{
    int idx = blockIdx.x * blockDim.x + threadIdx.x;
    if (idx >= total4) return;
    int c4 = idx & 31;
    int h  = (idx >> 5) & 7;
    int r  = idx >> 8;
    int b  = r >> 11;
    int t  = r & (TT - 1);
    float4 v = *(const float4*)(in + (size_t)r * rs + h * DD + c4 * 4);
    size_t ob = ((size_t)(b * HKV + h) * TT + t) * DD + c4 * 4;
    __nv_bfloat16 h0 = __float2bfloat16(v.x), h1 = __float2bfloat16(v.y);
    __nv_bfloat16 h2 = __float2bfloat16(v.z), h3 = __float2bfloat16(v.w);
    __nv_bfloat162 p0; p0.x = h0; p0.y = h1;
    __nv_bfloat162 p1; p1.x = h2; p1.y = h3;
    *(__nv_bfloat162*)(oh + ob)     = p0;
    *(__nv_bfloat162*)(oh + ob + 2) = p1;
    *(__nv_bfloat162*)(ol + ob)     = bfpair(v.x - __bfloat162float(h0),
                                             v.y - __bfloat162float(h1));
    *(__nv_bfloat162*)(ol + ob + 2) = bfpair(v.z - __bfloat162float(h2),
                                             v.w - __bfloat162float(h3));
}

// ======================= HMMA bf16-split GEMM ================================
#define GBM 128
#define GBN 128
#define GBK 32
#define GEMM_THREADS 256
#define ROW_BYTES 80
#define ARR_BYTES (128 * ROW_BYTES)
#define STAGE_BYTES (4 * ARR_BYTES)
#define GEMM_SMEM (2 * STAGE_BYTES)

__global__ void __launch_bounds__(GEMM_THREADS, 1)
gemm_mma_kernel(const __nv_bfloat16* __restrict__ Ahi, const __nv_bfloat16* __restrict__ Alo,
                const __nv_bfloat16* __restrict__ Bhi, const __nv_bfloat16* __restrict__ Blo,
                float* __restrict__ C, int M, int N, int K)
{
    extern __shared__ char smg[];
    const uint32_t sbase = smem_u32(smg);
    const int tid  = threadIdx.x;
    const int lane = tid & 31;
    const int wid  = tid >> 5;
    const int warp_m = wid >> 2;
    const int warp_n = wid & 3;
    const int m0 = blockIdx.y * GBM;
    const int n0 = blockIdx.x * GBN;

    const __nv_bfloat16* gsrc[4] = { Ahi, Alo, Bhi, Blo };

    auto load_stage = [&](int kt) {
        const int buf = kt & 1;
        const uint32_t sdst0 = sbase + buf * STAGE_BYTES;
        const int kofs = kt * GBK;
        #pragma unroll
        for (int i = 0; i < 8; i++) {
            int t   = tid + GEMM_THREADS * i;
            int arr = t >> 9;
            int rem = t & 511;
            int row = rem >> 2;
            int c   = rem & 3;
            int grow = (arr < 2) ? (m0 + row) : (n0 + row);
            const __nv_bfloat16* gp = gsrc[arr] + (size_t)grow * K + kofs + c * 8;
            cp_async16(sdst0 + arr * ARR_BYTES + row * ROW_BYTES + c * 16, gp);
        }
    };

    float acc[4][4][4];
    #pragma unroll
    for (int i = 0; i < 4; i++)
        #pragma unroll
        for (int j = 0; j < 4; j++)
            #pragma unroll
            for (int r = 0; r < 4; r++) acc[i][j][r] = 0.f;

    const int ktiles = K / GBK;

    load_stage(0);
    CP_COMMIT();

    const uint32_t a_row_b = (uint32_t)(warp_m * 64 + (lane & 15)) * ROW_BYTES
                           + ((lane >> 4) * 16);
    const uint32_t b_row_b = (uint32_t)(warp_n * 32 + ((lane >> 4) & 1) * 8 + (lane & 7)) * ROW_BYTES
                           + (((lane >> 3) & 1) * 16);

    for (int kt = 0; kt < ktiles; kt++) {
        if (kt + 1 < ktiles) { load_stage(kt + 1); CP_COMMIT(); CP_WAIT1(); }
        else { CP_WAIT0(); }
        __syncthreads();

        const uint32_t st = sbase + (kt & 1) * STAGE_BYTES;
        #pragma unroll
        for (int s = 0; s < 2; s++) {
            const uint32_t koff = s * 32;
            uint32_t ah[4][4], al[4][4];
            #pragma unroll
            for (int mt = 0; mt < 4; mt++) {
                uint32_t ad = st + a_row_b + mt * (16 * ROW_BYTES) + koff;
                ldsm4(ah[mt], ad);
                ldsm4(al[mt], ad + ARR_BYTES);
            }
            uint32_t bh[2][4], bl[2][4];
            #pragma unroll
            for (int np = 0; np < 2; np++) {
                uint32_t bd = st + 2 * ARR_BYTES + b_row_b + np * (16 * ROW_BYTES) + koff;
                ldsm4(bh[np], bd);
                ldsm4(bl[np], bd + ARR_BYTES);
            }
            #pragma unroll
            for (int mt = 0; mt < 4; mt++)
                #pragma unroll
                for (int nt = 0; nt < 4; nt++) {
                    const uint32_t* bhp = &bh[nt >> 1][(nt & 1) * 2];
                    const uint32_t* blp = &bl[nt >> 1][(nt & 1) * 2];
                    mma_bf16(acc[mt][nt], ah[mt], bhp);
                    mma_bf16(acc[mt][nt], ah[mt], blp);
                    mma_bf16(acc[mt][nt], al[mt], bhp);
                }
        }
        __syncthreads();
    }

    #pragma unroll
    for (int mt = 0; mt < 4; mt++) {
        int r0 = m0 + warp_m * 64 + mt * 16 + (lane >> 2);
        #pragma unroll
        for (int nt = 0; nt < 4; nt++) {
            int cbase = n0 + warp_n * 32 + nt * 8 + (lane & 3) * 2;
            float2 v0 = make_float2(acc[mt][nt][0], acc[mt][nt][1]);
            float2 v1 = make_float2(acc[mt][nt][2], acc[mt][nt][3]);
            *(float2*)(C + (size_t)r0 * N + cbase)       = v0;
            *(float2*)(C + (size_t)(r0 + 8) * N + cbase) = v1;
        }
    }
}

// ================= Flash attention: 4 warps x 32 Q rows, double-buffered KV ==
#define ABQ 128
#define ABK 64
#define AROW 136                       // padded row, bf16 elems (272 B)
#define AQH 0
#define AQL (ABQ*AROW)                 // 17408 elems
#define AKV0 (2*ABQ*AROW)              // 34816 elems
#define KVARR (ABK*AROW)               // 8704 elems per array
#define KVBUF (4*KVARR)                // Kh,Kl,Vh,Vl per buffer
#define ASM_ELEMS (AKV0 + 2*KVBUF)     // 104448
#define ASM_BYTES (ASM_ELEMS*2)        // 208896
#define ATTN_SCALE 0.08838834764831843f

__global__ void __launch_bounds__(128, 1)
attn_mma_kernel(const __nv_bfloat16* __restrict__ Qh, const __nv_bfloat16* __restrict__ Ql,
                const __nv_bfloat16* __restrict__ Kh, const __nv_bfloat16* __restrict__ Kl,
                const __nv_bfloat16* __restrict__ Vh, const __nv_bfloat16* __restrict__ Vl,
                __nv_bfloat16* __restrict__ Ohi, __nv_bfloat16* __restrict__ Olo)
{
    extern __shared__ __align__(1024) char smA[];
    const uint32_t sb = smem_u32(smA);

    const int tid  = threadIdx.x;
    const int lane = tid & 31;
    const int w    = tid >> 5;                     // 0..3, owns 32 Q rows
    const int qi   = gridDim.x - 1 - blockIdx.x;   // big tiles first
    const int h    = blockIdx.y;
    const int b    = blockIdx.z;
    const int hk   = h >> 1;
    const int qbase = qi * ABQ;

    const size_t qb0 = ((size_t)(b * HH + h) * TT + qbase) * DD;
    const size_t kb0 = ((size_t)(b * HKV + hk) * TT) * DD;
    const __nv_bfloat16* kvsrc[4] = { Kh, Kl, Vh, Vl };

    // ---- Q tile: cp.async bf16 hi/lo ----
    #pragma unroll
    for (int i = 0; i < 32; i++) {
        int task = tid + 128 * i;        // 0..4095
        int arr = task >> 11;            // 0 hi, 1 lo
        int rem = task & 2047;
        int row = rem >> 4;
        int c   = rem & 15;
        const __nv_bfloat16* src = (arr ? Ql : Qh) + qb0 + (size_t)row * DD + c * 8;
        cp_async16(sb + 2 * (uint32_t)((arr ? AQL : AQH) + row * AROW) + c * 16, src);
    }
    CP_COMMIT();

    const int ntiles = 2*qi + 2;

    auto load_kv = [&](int t, int buf) {
        const uint32_t base = sb + 2 * (uint32_t)(AKV0 + buf * KVBUF);
        const int k0 = t * ABK;
        #pragma unroll
        for (int i = 0; i < 32; i++) {
            int task = tid + 128 * i;    // 0..4095
            int arr = task >> 10;        // 0..3
            int rem = task & 1023;
            int row = rem >> 4;
            int c   = rem & 15;
            cp_async16(base + 2 * (uint32_t)(arr * KVARR + row * AROW) + c * 16,
                       kvsrc[arr] + kb0 + (size_t)(k0 + row) * DD + c * 8);
        }
        CP_COMMIT();
    };

    load_kv(0, 0);

    float mm[2][2], ll[2][2];
    #pragma unroll
    for (int mt = 0; mt < 2; mt++) { mm[mt][0] = mm[mt][1] = -INFINITY; ll[mt][0] = ll[mt][1] = 0.f; }
    float oacc[2][16][4];
    #pragma unroll
    for (int mt = 0; mt < 2; mt++)
        #pragma unroll
        for (int j = 0; j < 16; j++)
            #pragma unroll
            for (int r = 0; r < 4; r++) oacc[mt][j][r] = 0.f;

    // fragment address pieces
    uint32_t qA_h[2];
    #pragma unroll
    for (int mt = 0; mt < 2; mt++)
        qA_h[mt] = sb + 2*(uint32_t)(AQH + (w*32 + mt*16 + (lane & 15))*AROW) + (lane >> 4)*16;
    const uint32_t qHL = 2*(uint32_t)(AQL - AQH);
    const int krow  = ((lane >> 4) & 1)*8 + (lane & 7);
    const int kcolh = ((lane >> 3) & 1)*16;
    const int vrow  = ((lane >> 3) & 1)*8 + (lane & 7);
    const int vcolh = (lane >> 4)*16;

    for (int t = 0; t < ntiles; t++) {
        const int k0 = t * ABK;
        if (t + 1 < ntiles) { load_kv(t + 1, (t + 1) & 1); CP_WAIT1(); }
        else                { CP_WAIT0(); }
        __syncthreads();

        const uint32_t kvb = sb + 2 * (uint32_t)(AKV0 + (t & 1) * KVBUF);

        // ---- S = Q K^T (3 split passes, both mt tiles share K frags) ----
        float sacc[2][8][4];
        #pragma unroll
        for (int mt = 0; mt < 2; mt++)
            #pragma unroll
            for (int j = 0; j < 8; j++)
                #pragma unroll
                for (int r = 0; r < 4; r++) sacc[mt][j][r] = 0.f;

        #pragma unroll
        for (int s = 0; s < 8; s++) {
            uint32_t ah[2][4], al[2][4];
            #pragma unroll
            for (int mt = 0; mt < 2; mt++) {
                ldsm4(ah[mt], qA_h[mt] + s*32);
                ldsm4(al[mt], qA_h[mt] + s*32 + qHL);
            }
            #pragma unroll
            for (int jj = 0; jj < 4; jj++) {
                uint32_t kh[4], kl[4];
                uint32_t ka = kvb + 2*(uint32_t)((16*jj + krow)*AROW) + s*32 + kcolh;
                ldsm4(kh, ka);
                ldsm4(kl, ka + 2*(uint32_t)KVARR);
                #pragma unroll
                for (int mt = 0; mt < 2; mt++) {
                    mma_bf16(sacc[mt][2*jj],   ah[mt], &kh[0]);
                    mma_bf16(sacc[mt][2*jj],   ah[mt], &kl[0]);
                    mma_bf16(sacc[mt][2*jj],   al[mt], &kh[0]);
                    mma_bf16(sacc[mt][2*jj+1], ah[mt], &kh[2]);
                    mma_bf16(sacc[mt][2*jj+1], ah[mt], &kl[2]);
                    mma_bf16(sacc[mt][2*jj+1], al[mt], &kh[2]);
                }
            }
        }

        // ---- online softmax per mt tile ----
        const bool domask = (t >= ntiles - 2);
        float a_[2][2];
        #pragma unroll
        for (int mt = 0; mt < 2; mt++) {
            const int qr0 = qbase + w*32 + mt*16 + (lane >> 2);
            float mx0 = -INFINITY, mx1 = -INFINITY;
            #pragma unroll
            for (int j = 0; j < 8; j++) {
                #pragma unroll
                for (int r = 0; r < 4; r++) {
                    float sv = sacc[mt][j][r] * ATTN_SCALE;
                    if (domask) {
                        int col = k0 + 8*j + (lane & 3)*2 + (r & 1);
                        int qr  = qr0 + ((r >= 2) ? 8 : 0);
                        if (col > qr) sv = -INFINITY;
                    }
                    sacc[mt][j][r] = sv;
                    if (r < 2) mx0 = fmaxf(mx0, sv); else mx1 = fmaxf(mx1, sv);
                }
            }
            mx0 = fmaxf(mx0, __shfl_xor_sync(0xffffffffu, mx0, 1));
            mx0 = fmaxf(mx0, __shfl_xor_sync(0xffffffffu, mx0, 2));
            mx1 = fmaxf(mx1, __shfl_xor_sync(0xffffffffu, mx1, 1));
            mx1 = fmaxf(mx1, __shfl_xor_sync(0xffffffffu, mx1, 2));

            float m0n = fmaxf(mm[mt][0], mx0), m1n = fmaxf(mm[mt][1], mx1);
            float a0 = __expf(mm[mt][0] - m0n), a1 = __expf(mm[mt][1] - m1n);
            float ls0 = 0.f, ls1 = 0.f;
            #pragma unroll
            for (int j = 0; j < 8; j++) {
                float p0 = __expf(sacc[mt][j][0] - m0n);
                float p1 = __expf(sacc[mt][j][1] - m0n);
                float p2 = __expf(sacc[mt][j][2] - m1n);
                float p3 = __expf(sacc[mt][j][3] - m1n);
                sacc[mt][j][0] = p0; sacc[mt][j][1] = p1;
                sacc[mt][j][2] = p2; sacc[mt][j][3] = p3;
                ls0 += p0 + p1; ls1 += p2 + p3;
            }
            ls0 += __shfl_xor_sync(0xffffffffu, ls0, 1);
            ls0 += __shfl_xor_sync(0xffffffffu, ls0, 2);
            ls1 += __shfl_xor_sync(0xffffffffu, ls1, 1);
            ls1 += __shfl_xor_sync(0xffffffffu, ls1, 2);

            ll[mt][0] = ll[mt][0] * a0 + ls0;
            ll[mt][1] = ll[mt][1] * a1 + ls1;
            mm[mt][0] = m0n; mm[mt][1] = m1n;
            a_[mt][0] = a0; a_[mt][1] = a1;
            #pragma unroll
            for (int j = 0; j < 16; j++) {
                oacc[mt][j][0] *= a0; oacc[mt][j][1] *= a0;
                oacc[mt][j][2] *= a1; oacc[mt][j][3] *= a1;
            }
        }

        // ---- O += P V (V frags shared across mt) ----
        #pragma unroll
        for (int s2 = 0; s2 < 4; s2++) {
            uint32_t ahp[2][4], alp[2][4];
            #pragma unroll
            for (int mt = 0; mt < 2; mt++) {
                packsplit(sacc[mt][2*s2][0],   sacc[mt][2*s2][1],   ahp[mt][0], alp[mt][0]);
                packsplit(sacc[mt][2*s2][2],   sacc[mt][2*s2][3],   ahp[mt][1], alp[mt][1]);
                packsplit(sacc[mt][2*s2+1][0], sacc[mt][2*s2+1][1], ahp[mt][2], alp[mt][2]);
                packsplit(sacc[mt][2*s2+1][2], sacc[mt][2*s2+1][3], ahp[mt][3], alp[mt][3]);
            }
            uint32_t va = kvb + 2*(uint32_t)(2*KVARR + (16*s2 + vrow)*AROW) + vcolh;
            #pragma unroll
            for (int dd = 0; dd < 8; dd++) {
                uint32_t vh[4], vl[4];
                ldsm4t(vh, va + dd*32);
                ldsm4t(vl, va + dd*32 + 2*(uint32_t)KVARR);
                #pragma unroll
                for (int mt = 0; mt < 2; mt++) {
                    mma_bf16(oacc[mt][2*dd],   ahp[mt], &vh[0]);
                    mma_bf16(oacc[mt][2*dd],   ahp[mt], &vl[0]);
                    mma_bf16(oacc[mt][2*dd],   alp[mt], &vh[0]);
                    mma_bf16(oacc[mt][2*dd+1], ahp[mt], &vh[2]);
                    mma_bf16(oacc[mt][2*dd+1], ahp[mt], &vl[2]);
                    mma_bf16(oacc[mt][2*dd+1], alp[mt], &vh[2]);
                }
            }
        }
        __syncthreads();   // all reads of this KV buffer done before reuse
    }

    // ---- epilogue: normalize + write bf16 hi/lo ([b,t,h*d] layout for Wp) ----
    #pragma unroll
    for (int mt = 0; mt < 2; mt++) {
        float i0 = 1.f / ll[mt][0], i1 = 1.f / ll[mt][1];
        const int row0 = qbase + w*32 + mt*16 + (lane >> 2);
        const int col0 = (lane & 3)*2;
        #pragma unroll
        for (int j = 0; j < 16; j++) {
            int col = j*8 + col0;
            size_t base0 = ((size_t)(b*TT + row0)*HH + h)*DD + col;
            size_t base1 = base0 + (size_t)8*HH*DD;
            uint32_t hp, lp;
            packsplit(oacc[mt][j][0]*i0, oacc[mt][j][1]*i0, hp, lp);
            *(uint32_t*)(Ohi + base0) = hp;
            *(uint32_t*)(Olo + base0) = lp;
            packsplit(oacc[mt][j][2]*i1, oacc[mt][j][3]*i1, hp, lp);
            *(uint32_t*)(Ohi + base1) = hp;
            *(uint32_t*)(Olo + base1) = lp;
        }
    }
}

// ---------------- host entry -------------------------------------------------
extern "C" void kernel_launch(void* const* d_in, const int* in_sizes, int n_in,
                              void* d_out, int out_size)
{
    const float* x  = (const float*)d_in[0];
    const float* Wq = (const float*)d_in[1];
    const float* Wk = (const float*)d_in[2];
    const float* Wv = (const float*)d_in[3];
    const float* Wp = (const float*)d_in[4];
    float* out = (float*)d_out;

    float *q, *kv;
    cudaGetSymbolAddress((void**)&q, g_q);
    cudaGetSymbolAddress((void**)&kv, g_kv);

    __nv_bfloat16 *xhi, *xlo, *ohi, *olo, *wqh, *wql, *wkvh, *wkvl, *wph, *wpl;
    __nv_bfloat16 *qh, *ql, *kh, *kl, *vh, *vl;
    cudaGetSymbolAddress((void**)&xhi, g_xhi);  cudaGetSymbolAddress((void**)&xlo, g_xlo);
    cudaGetSymbolAddress((void**)&ohi, g_ohi);  cudaGetSymbolAddress((void**)&olo, g_olo);
    cudaGetSymbolAddress((void**)&wqh, g_wqh);  cudaGetSymbolAddress((void**)&wql, g_wql);
    cudaGetSymbolAddress((void**)&wkvh, g_wkvh); cudaGetSymbolAddress((void**)&wkvl, g_wkvl);
    cudaGetSymbolAddress((void**)&wph, g_wph);  cudaGetSymbolAddress((void**)&wpl, g_wpl);
    cudaGetSymbolAddress((void**)&qh, g_qh);    cudaGetSymbolAddress((void**)&ql, g_ql);
    cudaGetSymbolAddress((void**)&kh, g_kh);    cudaGetSymbolAddress((void**)&kl, g_kl);
    cudaGetSymbolAddress((void**)&vh, g_vh);    cudaGetSymbolAddress((void**)&vl, g_vl);

    cudaFuncSetAttribute(gemm_mma_kernel, cudaFuncAttributeMaxDynamicSharedMemorySize, GEMM_SMEM);
    cudaFuncSetAttribute(attn_mma_kernel, cudaFuncAttributeMaxDynamicSharedMemorySize, ASM_BYTES);

    // (0) split x into bf16 hi/lo
    {
        int n4 = (NROW * CC) / 4;
        split_kernel<<<(n4 + 255) / 256, 256>>>((const float4*)x,
            (__nv_bfloat162*)xhi, (__nv_bfloat162*)xlo, n4);
    }
    // (1) transpose + split Wq
    transpose_split_kernel<<<dim3(CC/32, CC/32), dim3(32, 8)>>>(Wq, wqh, wql, CC, CC);
    // (2,3) transpose + split Wk, Wv into combined buffer (rows 0..1023 / 1024..2047)
    transpose_split_kernel<<<dim3((HKV*DD)/32, CC/32), dim3(32, 8)>>>(Wk, wkvh, wkvl, CC, HKV*DD);
    transpose_split_kernel<<<dim3((HKV*DD)/32, CC/32), dim3(32, 8)>>>(
        Wv, wkvh + (size_t)(HKV*DD) * CC, wkvl + (size_t)(HKV*DD) * CC, CC, HKV*DD);

    // (4) Q projection  <- ncu capture slot
    gemm_mma_kernel<<<dim3(CC/GBN, NROW/GBM), GEMM_THREADS, GEMM_SMEM>>>(xhi, xlo, wqh, wql, q, NROW, CC, CC);
    // (5) combined KV projection
    gemm_mma_kernel<<<dim3(CC/GBN, NROW/GBM), GEMM_THREADS, GEMM_SMEM>>>(xhi, xlo, wkvh, wkvl, kv, NROW, CC, CC);

    // (6-8) RoPE + split + head-major relayout
    {
        int totq = NROW * HH * 64;
        rope_split_kernel<<<(totq + 255) / 256, 256>>>(q, qh, ql, HH, CC, totq);
        int totk = NROW * HKV * 64;
        rope_split_kernel<<<(totk + 255) / 256, 256>>>(kv, kh, kl, HKV, CC, totk);
        int totv = NROW * HKV * 32;
        v_split_kernel<<<(totv + 255) / 256, 256>>>(kv + HKV*DD, vh, vl, CC, totv);
    }

    // (9) attention
    attn_mma_kernel<<<dim3(TT / ABQ, HH, BB), 128, ASM_BYTES>>>(qh, ql, kh, kl, vh, vl, ohi, olo);

    // (10) transpose + split Wp (deferred: only needed now)
    transpose_split_kernel<<<dim3(CC/32, CC/32), dim3(32, 8)>>>(Wp, wph, wpl, CC, CC);

    // (11) output projection
    gemm_mma_kernel<<<dim3(CC/GBN, NROW/GBM), GEMM_THREADS, GEMM_SMEM>>>(ohi, olo, wph, wpl, out, NROW, CC, CC);
}

// round 7
// speedup vs baseline: 1.1274x; 1.1274x over previous
#include <cuda_runtime.h>
#include <cuda_bf16.h>
#include <math.h>
#include <cstdint>

// Problem constants
#define BB 2
#define TT 2048
#define CC 2048
#define HH 16
#define HKV 8
#define DD 128
#define NROW (BB*TT)          // 4096

// ---------------- scratch (device globals; no allocation allowed) ----------
__device__ float g_q[(size_t)NROW * CC];
__device__ float g_kv[(size_t)NROW * CC];      // cols 0..1023 = k, 1024..2047 = v

__device__ __align__(16) __nv_bfloat16 g_xhi[(size_t)NROW * CC];
__device__ __align__(16) __nv_bfloat16 g_xlo[(size_t)NROW * CC];
__device__ __align__(16) __nv_bfloat16 g_ohi[(size_t)NROW * CC];
__device__ __align__(16) __nv_bfloat16 g_olo[(size_t)NROW * CC];
__device__ __align__(16) __nv_bfloat16 g_wqh[(size_t)CC * CC];
__device__ __align__(16) __nv_bfloat16 g_wql[(size_t)CC * CC];
__device__ __align__(16) __nv_bfloat16 g_wph[(size_t)CC * CC];
__device__ __align__(16) __nv_bfloat16 g_wpl[(size_t)CC * CC];
__device__ __align__(16) __nv_bfloat16 g_wkvh[(size_t)CC * CC];
__device__ __align__(16) __nv_bfloat16 g_wkvl[(size_t)CC * CC];

// head-major bf16 hi/lo Q/K/V for attention
__device__ __align__(16) __nv_bfloat16 g_qh[(size_t)BB * HH * TT * DD];
__device__ __align__(16) __nv_bfloat16 g_ql[(size_t)BB * HH * TT * DD];
__device__ __align__(16) __nv_bfloat16 g_kh[(size_t)BB * HKV * TT * DD];
__device__ __align__(16) __nv_bfloat16 g_kl[(size_t)BB * HKV * TT * DD];
__device__ __align__(16) __nv_bfloat16 g_vh[(size_t)BB * HKV * TT * DD];
__device__ __align__(16) __nv_bfloat16 g_vl[(size_t)BB * HKV * TT * DD];

// ======================= low-level helpers ==================================
__device__ __forceinline__ uint32_t smem_u32(const void* p) {
    uint32_t a;
    asm("{ .reg .u64 t; cvta.to.shared.u64 t, %1; cvt.u32.u64 %0, t; }"
        : "=r"(a) : "l"(p));
    return a;
}
__device__ __forceinline__ void ldsm4(uint32_t* r, uint32_t addr) {
    asm volatile("ldmatrix.sync.aligned.m8n8.x4.shared.b16 {%0,%1,%2,%3}, [%4];"
        : "=r"(r[0]), "=r"(r[1]), "=r"(r[2]), "=r"(r[3]) : "r"(addr));
}
__device__ __forceinline__ void ldsm4t(uint32_t* r, uint32_t addr) {
    asm volatile("ldmatrix.sync.aligned.m8n8.x4.trans.shared.b16 {%0,%1,%2,%3}, [%4];"
        : "=r"(r[0]), "=r"(r[1]), "=r"(r[2]), "=r"(r[3]) : "r"(addr));
}
__device__ __forceinline__ void mma_bf16(float* d, const uint32_t* a, const uint32_t* b) {
    asm volatile(
        "mma.sync.aligned.m16n8k16.row.col.f32.bf16.bf16.f32 "
        "{%0,%1,%2,%3}, {%4,%5,%6,%7}, {%8,%9}, {%0,%1,%2,%3};"
        : "+f"(d[0]), "+f"(d[1]), "+f"(d[2]), "+f"(d[3])
        : "r"(a[0]), "r"(a[1]), "r"(a[2]), "r"(a[3]), "r"(b[0]), "r"(b[1]));
}
__device__ __forceinline__ void cp_async16(uint32_t dst, const void* src) {
    asm volatile("cp.async.cg.shared.global [%0], [%1], 16;\n" :: "r"(dst), "l"(src));
}
#define CP_COMMIT() asm volatile("cp.async.commit_group;\n" ::: "memory")
#define CP_WAIT2()  asm volatile("cp.async.wait_group 2;\n" ::: "memory")
#define CP_WAIT1()  asm volatile("cp.async.wait_group 1;\n" ::: "memory")
#define CP_WAIT0()  asm volatile("cp.async.wait_group 0;\n" ::: "memory")

__device__ __forceinline__ __nv_bfloat162 bfpair(float a, float b) {
    __nv_bfloat162 r; r.x = __float2bfloat16(a); r.y = __float2bfloat16(b); return r;
}
__device__ __forceinline__ void packsplit(float a, float b, uint32_t& hi, uint32_t& lo) {
    __nv_bfloat16 ha = __float2bfloat16(a), hb = __float2bfloat16(b);
    __nv_bfloat162 H; H.x = ha; H.y = hb;
    __nv_bfloat162 L;
    L.x = __float2bfloat16(a - __bfloat162float(ha));
    L.y = __float2bfloat16(b - __bfloat162float(hb));
    hi = *(uint32_t*)&H; lo = *(uint32_t*)&L;
}

// ======================= conversion kernels =================================
__global__ void split_kernel(const float4* __restrict__ in,
                             __nv_bfloat162* __restrict__ hi,
                             __nv_bfloat162* __restrict__ lo, int n4)
{
    int i = blockIdx.x * blockDim.x + threadIdx.x;
    if (i >= n4) return;
    float4 v = in[i];
    __nv_bfloat16 h0 = __float2bfloat16(v.x);
    __nv_bfloat16 h1 = __float2bfloat16(v.y);
    __nv_bfloat16 h2 = __float2bfloat16(v.z);
    __nv_bfloat16 h3 = __float2bfloat16(v.w);
    __nv_bfloat162 ph0; ph0.x = h0; ph0.y = h1;
    __nv_bfloat162 ph1; ph1.x = h2; ph1.y = h3;
    hi[2*i]   = ph0;
    hi[2*i+1] = ph1;
    __nv_bfloat162 pl0, pl1;
    pl0.x = __float2bfloat16(v.x - __bfloat162float(h0));
    pl0.y = __float2bfloat16(v.y - __bfloat162float(h1));
    pl1.x = __float2bfloat16(v.z - __bfloat162float(h2));
    pl1.y = __float2bfloat16(v.w - __bfloat162float(h3));
    lo[2*i]   = pl0;
    lo[2*i+1] = pl1;
}

// W: [K, N] row-major -> T{hi,lo}: [N, K] row-major (bf16 hi/lo split)
__global__ void transpose_split_kernel(const float* __restrict__ W,
                                       __nv_bfloat16* __restrict__ Thi,
                                       __nv_bfloat16* __restrict__ Tlo,
                                       int K, int N)
{
    __shared__ float t[32][33];
    int n0 = blockIdx.x * 32, k0 = blockIdx.y * 32;
    int tx = threadIdx.x, ty = threadIdx.y;   // (32, 8)
    #pragma unroll
    for (int j = 0; j < 32; j += 8)
        t[ty + j][tx] = W[(size_t)(k0 + ty + j) * N + n0 + tx];
    __syncthreads();
    #pragma unroll
    for (int j = 0; j < 32; j += 8) {
        float v = t[tx][ty + j];
        __nv_bfloat16 h = __float2bfloat16(v);
        __nv_bfloat16 l = __float2bfloat16(v - __bfloat162float(h));
        size_t oidx = (size_t)(n0 + ty + j) * K + k0 + tx;
        Thi[oidx] = h;
        Tlo[oidx] = l;
    }
}

// RoPE + bf16 hi/lo split + relayout [b,t,h,d] -> [b,h,t,d]; rs = input row stride
__global__ void rope_split_kernel(const float* __restrict__ in,
                                  __nv_bfloat16* __restrict__ oh,
                                  __nv_bfloat16* __restrict__ ol,
                                  int n_heads, int rs, int total)
{
    int idx = blockIdx.x * blockDim.x + threadIdx.x;
    if (idx >= total) return;
    int j = idx & 63;
    int h = (idx >> 6) % n_heads;
    int r = idx / (64 * n_heads);
    int b = r >> 11;
    int t = r & (TT - 1);

    float e = (float)(2 * j) * (1.0f / 128.0f);
    float inv = 1.0f / powf(10000.0f, e);
    float f = (float)t * inv;
    float c = cosf(f), s = sinf(f);

    const float* p = in + (size_t)r * rs + h * DD;
    float x1 = p[j], x2 = p[j + 64];
    float y1 = x1 * c - x2 * s;
    float y2 = x2 * c + x1 * s;

    size_t ob = ((size_t)(b * n_heads + h) * TT + t) * DD + j;
    __nv_bfloat16 h1 = __float2bfloat16(y1);
    __nv_bfloat16 h2 = __float2bfloat16(y2);
    oh[ob]      = h1;
    oh[ob + 64] = h2;
    ol[ob]      = __float2bfloat16(y1 - __bfloat162float(h1));
    ol[ob + 64] = __float2bfloat16(y2 - __bfloat162float(h2));
}

// V: bf16 hi/lo split + relayout [b,t,hk,d] -> [b,hk,t,d]; rs = input row stride
__global__ void v_split_kernel(const float* __restrict__ in,
                               __nv_bfloat16* __restrict__ oh,
                               __nv_bfloat16* __restrict__ ol, int rs, int total4)
{
    int idx = blockIdx.x * blockDim.x + threadIdx.x;
    if (idx >= total4) return;
    int c4 = idx & 31;
    int h  = (idx >> 5) & 7;
    int r  = idx >> 8;
    int b  = r >> 11;
    int t  = r & (TT - 1);
    float4 v = *(const float4*)(in + (size_t)r * rs + h * DD + c4 * 4);
    size_t ob = ((size_t)(b * HKV + h) * TT + t) * DD + c4 * 4;
    __nv_bfloat16 h0 = __float2bfloat16(v.x), h1 = __float2bfloat16(v.y);
    __nv_bfloat16 h2 = __float2bfloat16(v.z), h3 = __float2bfloat16(v.w);
    __nv_bfloat162 p0; p0.x = h0; p0.y = h1;
    __nv_bfloat162 p1; p1.x = h2; p1.y = h3;
    *(__nv_bfloat162*)(oh + ob)     = p0;
    *(__nv_bfloat162*)(oh + ob + 2) = p1;
    *(__nv_bfloat162*)(ol + ob)     = bfpair(v.x - __bfloat162float(h0),
                                             v.y - __bfloat162float(h1));
    *(__nv_bfloat162*)(ol + ob + 2) = bfpair(v.z - __bfloat162float(h2),
                                             v.w - __bfloat162float(h3));
}

// ======================= HMMA bf16-split GEMM (128x256 CTA, 3-stage) ========
#define GBM 128
#define GBN 256
#define GBK 32
#define GEMM_THREADS 256
#define ROW_BYTES 80
#define ARR_A (128 * ROW_BYTES)            // 10240
#define ARR_B (256 * ROW_BYTES)            // 20480
#define STAGE_BYTES (2*ARR_A + 2*ARR_B)    // 61440  (Ahi, Alo, Bhi, Blo)
#define OFF_AH 0
#define OFF_AL ARR_A
#define OFF_BH (2*ARR_A)
#define OFF_BL (2*ARR_A + ARR_B)
#define GEMM_SMEM (3 * STAGE_BYTES)        // 184320

__global__ void __launch_bounds__(GEMM_THREADS, 1)
gemm_mma_kernel(const __nv_bfloat16* __restrict__ Ahi, const __nv_bfloat16* __restrict__ Alo,
                const __nv_bfloat16* __restrict__ Bhi, const __nv_bfloat16* __restrict__ Blo,
                float* __restrict__ C, int M, int N, int K)
{
    extern __shared__ char smg[];
    const uint32_t sbase = smem_u32(smg);
    const int tid  = threadIdx.x;
    const int lane = tid & 31;
    const int wid  = tid >> 5;
    const int warp_m = wid >> 2;     // 0..1 (64 rows)
    const int warp_n = wid & 3;      // 0..3 (64 cols)
    const int m0 = blockIdx.y * GBM;
    const int n0 = blockIdx.x * GBN;

    // stage loader: 3072 16B-chunks, 12 per thread
    auto load_stage = [&](int kt) {
        const uint32_t sdst = sbase + (kt % 3) * STAGE_BYTES;
        const int kofs = kt * GBK;
        #pragma unroll
        for (int i = 0; i < 12; i++) {
            int task = tid + GEMM_THREADS * i;   // 0..3071
            if (task < 1024) {
                int arr = task >> 9;             // 0 Ahi, 1 Alo
                int rem = task & 511;
                int row = rem >> 2, c = rem & 3;
                const __nv_bfloat16* gp = (arr ? Alo : Ahi) + (size_t)(m0+row)*K + kofs + c*8;
                cp_async16(sdst + (arr ? OFF_AL : OFF_AH) + row*ROW_BYTES + c*16, gp);
            } else {
                int t2  = task - 1024;           // 0..2047
                int arr = t2 >> 10;              // 0 Bhi, 1 Blo
                int rem = t2 & 1023;
                int row = rem >> 2, c = rem & 3;
                const __nv_bfloat16* gp = (arr ? Blo : Bhi) + (size_t)(n0+row)*K + kofs + c*8;
                cp_async16(sdst + (arr ? OFF_BL : OFF_BH) + row*ROW_BYTES + c*16, gp);
            }
        }
        CP_COMMIT();
    };

    float acc[4][8][4];
    #pragma unroll
    for (int i = 0; i < 4; i++)
        #pragma unroll
        for (int j = 0; j < 8; j++)
            #pragma unroll
            for (int r = 0; r < 4; r++) acc[i][j][r] = 0.f;

    const int ktiles = K / GBK;

    load_stage(0);
    load_stage(1);

    const uint32_t a_row_b = (uint32_t)(warp_m * 64 + (lane & 15)) * ROW_BYTES
                           + ((lane >> 4) * 16);
    const uint32_t b_row_b = (uint32_t)(warp_n * 64 + ((lane >> 4) & 1) * 8 + (lane & 7)) * ROW_BYTES
                           + (((lane >> 3) & 1) * 16);

    for (int kt = 0; kt < ktiles; kt++) {
        if (kt + 2 < ktiles) { load_stage(kt + 2); CP_WAIT2(); }
        else if (kt + 1 < ktiles) { CP_WAIT1(); }
        else { CP_WAIT0(); }
        __syncthreads();

        const uint32_t st = sbase + (kt % 3) * STAGE_BYTES;
        #pragma unroll
        for (int s = 0; s < 2; s++) {          // two k16 steps
            const uint32_t koff = s * 32;
            uint32_t ah[4][4], al[4][4];
            #pragma unroll
            for (int mt = 0; mt < 4; mt++) {
                uint32_t ad = st + OFF_AH + a_row_b + mt * (16 * ROW_BYTES) + koff;
                ldsm4(ah[mt], ad);
                ldsm4(al[mt], ad + ARR_A);
            }
            uint32_t bh[4][4], bl[4][4];
            #pragma unroll
            for (int np = 0; np < 4; np++) {
                uint32_t bd = st + OFF_BH + b_row_b + np * (16 * ROW_BYTES) + koff;
                ldsm4(bh[np], bd);
                ldsm4(bl[np], bd + ARR_B);
            }
            #pragma unroll
            for (int mt = 0; mt < 4; mt++)
                #pragma unroll
                for (int nt = 0; nt < 8; nt++) {
                    const uint32_t* bhp = &bh[nt >> 1][(nt & 1) * 2];
                    const uint32_t* blp = &bl[nt >> 1][(nt & 1) * 2];
                    mma_bf16(acc[mt][nt], ah[mt], bhp);
                    mma_bf16(acc[mt][nt], ah[mt], blp);
                    mma_bf16(acc[mt][nt], al[mt], bhp);
                }
        }
        __syncthreads();
    }

    #pragma unroll
    for (int mt = 0; mt < 4; mt++) {
        int r0 = m0 + warp_m * 64 + mt * 16 + (lane >> 2);
        #pragma unroll
        for (int nt = 0; nt < 8; nt++) {
            int cbase = n0 + warp_n * 64 + nt * 8 + (lane & 3) * 2;
            float2 v0 = make_float2(acc[mt][nt][0], acc[mt][nt][1]);
            float2 v1 = make_float2(acc[mt][nt][2], acc[mt][nt][3]);
            *(float2*)(C + (size_t)r0 * N + cbase)       = v0;
            *(float2*)(C + (size_t)(r0 + 8) * N + cbase) = v1;
        }
    }
}

// ================= Flash attention on HMMA (R5 config: 8 warps x 16 rows) ====
#define ABQ 128
#define ABK 64
#define AROW 136                       // bf16 elements per padded row (272B)
#define AQH 0
#define AQL (ABQ*AROW)
#define AKH (2*ABQ*AROW)
#define AKL (AKH + ABK*AROW)
#define AVH (AKL + ABK*AROW)
#define AVL (AVH + ABK*AROW)
#define ASM_ELEMS (AVL + ABK*AROW)
#define ASM_BYTES (ASM_ELEMS*2)        // 139264
#define ATTN_SCALE 0.08838834764831843f

__global__ void __launch_bounds__(256, 1)
attn_mma_kernel(const __nv_bfloat16* __restrict__ Qh, const __nv_bfloat16* __restrict__ Ql,
                const __nv_bfloat16* __restrict__ Kh, const __nv_bfloat16* __restrict__ Kl,
                const __nv_bfloat16* __restrict__ Vh, const __nv_bfloat16* __restrict__ Vl,
                __nv_bfloat16* __restrict__ Ohi, __nv_bfloat16* __restrict__ Olo)
{
    extern __shared__ __align__(1024) char smA[];
    const uint32_t sb = smem_u32(smA);

    const int tid  = threadIdx.x;
    const int lane = tid & 31;
    const int w    = tid >> 5;
    const int qi   = gridDim.x - 1 - blockIdx.x;   // big tiles first
    const int h    = blockIdx.y;
    const int b    = blockIdx.z;
    const int hk   = h >> 1;
    const int qbase = qi * ABQ;

    const size_t qb0 = ((size_t)(b * HH + h) * TT + qbase) * DD;
    const size_t kb0 = ((size_t)(b * HKV + hk) * TT) * DD;
    const __nv_bfloat16* kvsrc[4] = { Kh, Kl, Vh, Vl };

    // ---- Q tile: cp.async bf16 hi/lo ----
    #pragma unroll
    for (int i = 0; i < 16; i++) {
        int task = tid + 256 * i;        // 0..4095
        int arr = task >> 11;            // 0 hi, 1 lo
        int rem = task & 2047;
        int row = rem >> 4;
        int c   = rem & 15;
        const __nv_bfloat16* src = (arr ? Ql : Qh) + qb0 + (size_t)row * DD + c * 8;
        cp_async16(sb + 2 * (uint32_t)((arr ? AQL : AQH) + row * AROW) + c * 16, src);
    }
    CP_COMMIT();

    float m0 = -INFINITY, m1 = -INFINITY, l0 = 0.f, l1 = 0.f;
    float oacc[16][4];
    #pragma unroll
    for (int j = 0; j < 16; j++)
        #pragma unroll
        for (int r = 0; r < 4; r++) oacc[j][r] = 0.f;

    const uint32_t qA_h = sb + 2*(uint32_t)(AQH + (w*16 + (lane & 15))*AROW) + (lane >> 4)*16;
    const uint32_t qA_l = qA_h + 2*(uint32_t)(AQL - AQH);
    const int krow  = ((lane >> 4) & 1)*8 + (lane & 7);
    const int kcolh = ((lane >> 3) & 1)*16;
    const int vrow  = ((lane >> 3) & 1)*8 + (lane & 7);
    const int vcolh = (lane >> 4)*16;

    const int ntiles = 2*qi + 2;
    const int qr0 = qbase + w*16 + (lane >> 2);

    for (int t = 0; t < ntiles; t++) {
        const int k0 = t * ABK;
        __syncthreads();   // prev tile's smem reads done before overwrite

        // ---- K tile (group), then V tile (group) ----
        #pragma unroll
        for (int i = 0; i < 8; i++) {
            int task = tid + 256 * i;
            int arr = task >> 10;
            int rem = task & 1023;
            int row = rem >> 4;
            int c   = rem & 15;
            cp_async16(sb + 2*(uint32_t)(AKH + arr*(ABK*AROW) + row*AROW) + c*16,
                       kvsrc[arr] + kb0 + (size_t)(k0 + row)*DD + c*8);
        }
        CP_COMMIT();
        #pragma unroll
        for (int i = 8; i < 16; i++) {
            int task = tid + 256 * i;
            int arr = task >> 10;
            int rem = task & 1023;
            int row = rem >> 4;
            int c   = rem & 15;
            cp_async16(sb + 2*(uint32_t)(AKH + arr*(ABK*AROW) + row*AROW) + c*16,
                       kvsrc[arr] + kb0 + (size_t)(k0 + row)*DD + c*8);
        }
        CP_COMMIT();

        CP_WAIT1();          // Q + K complete (V may still be in flight)
        __syncthreads();

        // ---- S = Q K^T (3 split passes) ----
        float sacc[8][4];
        #pragma unroll
        for (int j = 0; j < 8; j++)
            #pragma unroll
            for (int r = 0; r < 4; r++) sacc[j][r] = 0.f;

        #pragma unroll
        for (int s = 0; s < 8; s++) {
            uint32_t ah[4], al[4];
            ldsm4(ah, qA_h + s*32);
            ldsm4(al, qA_l + s*32);
            #pragma unroll
            for (int jj = 0; jj < 4; jj++) {
                uint32_t kh[4], kl[4];
                uint32_t ka = sb + 2*(uint32_t)(AKH + (16*jj + krow)*AROW) + s*32 + kcolh;
                ldsm4(kh, ka);
                ldsm4(kl, ka + 2*(uint32_t)(AKL - AKH));
                mma_bf16(sacc[2*jj],   ah, &kh[0]);
                mma_bf16(sacc[2*jj],   ah, &kl[0]);
                mma_bf16(sacc[2*jj],   al, &kh[0]);
                mma_bf16(sacc[2*jj+1], ah, &kh[2]);
                mma_bf16(sacc[2*jj+1], ah, &kl[2]);
                mma_bf16(sacc[2*jj+1], al, &kh[2]);
            }
        }

        CP_WAIT0();          // V tile complete
        __syncthreads();

        // ---- online softmax ----
        const bool domask = (t >= ntiles - 2);
        float mx0 = -INFINITY, mx1 = -INFINITY;
        #pragma unroll
        for (int j = 0; j < 8; j++) {
            #pragma unroll
            for (int r = 0; r < 4; r++) {
                float sv = sacc[j][r] * ATTN_SCALE;
                if (domask) {
                    int col = k0 + 8*j + (lane & 3)*2 + (r & 1);
                    int qr  = qr0 + ((r >= 2) ? 8 : 0);
                    if (col > qr) sv = -INFINITY;
                }
                sacc[j][r] = sv;
                if (r < 2) mx0 = fmaxf(mx0, sv); else mx1 = fmaxf(mx1, sv);
            }
        }
        mx0 = fmaxf(mx0, __shfl_xor_sync(0xffffffffu, mx0, 1));
        mx0 = fmaxf(mx0, __shfl_xor_sync(0xffffffffu, mx0, 2));
        mx1 = fmaxf(mx1, __shfl_xor_sync(0xffffffffu, mx1, 1));
        mx1 = fmaxf(mx1, __shfl_xor_sync(0xffffffffu, mx1, 2));

        float m0n = fmaxf(m0, mx0), m1n = fmaxf(m1, mx1);
        float a0 = __expf(m0 - m0n), a1 = __expf(m1 - m1n);
        float ls0 = 0.f, ls1 = 0.f;
        #pragma unroll
        for (int j = 0; j < 8; j++) {
            float p0 = __expf(sacc[j][0] - m0n);
            float p1 = __expf(sacc[j][1] - m0n);
            float p2 = __expf(sacc[j][2] - m1n);
            float p3 = __expf(sacc[j][3] - m1n);
            sacc[j][0] = p0; sacc[j][1] = p1; sacc[j][2] = p2; sacc[j][3] = p3;
            ls0 += p0 + p1; ls1 += p2 + p3;
        }
        ls0 += __shfl_xor_sync(0xffffffffu, ls0, 1);
        ls0 += __shfl_xor_sync(0xffffffffu, ls0, 2);
        ls1 += __shfl_xor_sync(0xffffffffu, ls1, 1);
        ls1 += __shfl_xor_sync(0xffffffffu, ls1, 2);

        l0 = l0 * a0 + ls0;
        l1 = l1 * a1 + ls1;
        m0 = m0n; m1 = m1n;
        #pragma unroll
        for (int j = 0; j < 16; j++) {
            oacc[j][0] *= a0; oacc[j][1] *= a0;
            oacc[j][2] *= a1; oacc[j][3] *= a1;
        }

        // ---- O += P V (3 split passes, P from registers) ----
        #pragma unroll
        for (int s2 = 0; s2 < 4; s2++) {
            uint32_t ahp[4], alp[4];
            packsplit(sacc[2*s2][0],   sacc[2*s2][1],   ahp[0], alp[0]);
            packsplit(sacc[2*s2][2],   sacc[2*s2][3],   ahp[1], alp[1]);
            packsplit(sacc[2*s2+1][0], sacc[2*s2+1][1], ahp[2], alp[2]);
            packsplit(sacc[2*s2+1][2], sacc[2*s2+1][3], ahp[3], alp[3]);
            uint32_t va = sb + 2*(uint32_t)(AVH + (16*s2 + vrow)*AROW) + vcolh;
            #pragma unroll
            for (int dd = 0; dd < 8; dd++) {
                uint32_t vh[4], vl[4];
                ldsm4t(vh, va + dd*32);
                ldsm4t(vl, va + dd*32 + 2*(uint32_t)(AVL - AVH));
                mma_bf16(oacc[2*dd],   ahp, &vh[0]);
                mma_bf16(oacc[2*dd],   ahp, &vl[0]);
                mma_bf16(oacc[2*dd],   alp, &vh[0]);
                mma_bf16(oacc[2*dd+1], ahp, &vh[2]);
                mma_bf16(oacc[2*dd+1], ahp, &vl[2]);
                mma_bf16(oacc[2*dd+1], alp, &vh[2]);
            }
        }
    }

    // ---- epilogue: normalize + write bf16 hi/lo ([b,t,h*d] for Wp GEMM) ----
    float i0 = 1.f / l0, i1 = 1.f / l1;
    const int row0 = qbase + w*16 + (lane >> 2);
    const int col0 = (lane & 3)*2;
    #pragma unroll
    for (int j = 0; j < 16; j++) {
        int col = j*8 + col0;
        size_t base0 = ((size_t)(b*TT + row0)*HH + h)*DD + col;
        size_t base1 = base0 + (size_t)8*HH*DD;
        uint32_t hp, lp;
        packsplit(oacc[j][0]*i0, oacc[j][1]*i0, hp, lp);
        *(uint32_t*)(Ohi + base0) = hp;
        *(uint32_t*)(Olo + base0) = lp;
        packsplit(oacc[j][2]*i1, oacc[j][3]*i1, hp, lp);
        *(uint32_t*)(Ohi + base1) = hp;
        *(uint32_t*)(Olo + base1) = lp;
    }
}

// ---------------- host entry -------------------------------------------------
extern "C" void kernel_launch(void* const* d_in, const int* in_sizes, int n_in,
                              void* d_out, int out_size)
{
    const float* x  = (const float*)d_in[0];
    const float* Wq = (const float*)d_in[1];
    const float* Wk = (const float*)d_in[2];
    const float* Wv = (const float*)d_in[3];
    const float* Wp = (const float*)d_in[4];
    float* out = (float*)d_out;

    float *q, *kv;
    cudaGetSymbolAddress((void**)&q, g_q);
    cudaGetSymbolAddress((void**)&kv, g_kv);

    __nv_bfloat16 *xhi, *xlo, *ohi, *olo, *wqh, *wql, *wkvh, *wkvl, *wph, *wpl;
    __nv_bfloat16 *qh, *ql, *kh, *kl, *vh, *vl;
    cudaGetSymbolAddress((void**)&xhi, g_xhi);  cudaGetSymbolAddress((void**)&xlo, g_xlo);
    cudaGetSymbolAddress((void**)&ohi, g_ohi);  cudaGetSymbolAddress((void**)&olo, g_olo);
    cudaGetSymbolAddress((void**)&wqh, g_wqh);  cudaGetSymbolAddress((void**)&wql, g_wql);
    cudaGetSymbolAddress((void**)&wkvh, g_wkvh); cudaGetSymbolAddress((void**)&wkvl, g_wkvl);
    cudaGetSymbolAddress((void**)&wph, g_wph);  cudaGetSymbolAddress((void**)&wpl, g_wpl);
    cudaGetSymbolAddress((void**)&qh, g_qh);    cudaGetSymbolAddress((void**)&ql, g_ql);
    cudaGetSymbolAddress((void**)&kh, g_kh);    cudaGetSymbolAddress((void**)&kl, g_kl);
    cudaGetSymbolAddress((void**)&vh, g_vh);    cudaGetSymbolAddress((void**)&vl, g_vl);

    cudaFuncSetAttribute(gemm_mma_kernel, cudaFuncAttributeMaxDynamicSharedMemorySize, GEMM_SMEM);
    cudaFuncSetAttribute(attn_mma_kernel, cudaFuncAttributeMaxDynamicSharedMemorySize, ASM_BYTES);

    // (0) split x into bf16 hi/lo
    {
        int n4 = (NROW * CC) / 4;
        split_kernel<<<(n4 + 255) / 256, 256>>>((const float4*)x,
            (__nv_bfloat162*)xhi, (__nv_bfloat162*)xlo, n4);
    }
    // (1-3) transpose + split weights
    transpose_split_kernel<<<dim3(CC/32, CC/32), dim3(32, 8)>>>(Wq, wqh, wql, CC, CC);
    transpose_split_kernel<<<dim3((HKV*DD)/32, CC/32), dim3(32, 8)>>>(Wk, wkvh, wkvl, CC, HKV*DD);
    transpose_split_kernel<<<dim3((HKV*DD)/32, CC/32), dim3(32, 8)>>>(
        Wv, wkvh + (size_t)(HKV*DD) * CC, wkvl + (size_t)(HKV*DD) * CC, CC, HKV*DD);

    // (4) Q projection, (5) combined KV projection
    gemm_mma_kernel<<<dim3(CC/GBN, NROW/GBM), GEMM_THREADS, GEMM_SMEM>>>(xhi, xlo, wqh, wql, q, NROW, CC, CC);
    gemm_mma_kernel<<<dim3(CC/GBN, NROW/GBM), GEMM_THREADS, GEMM_SMEM>>>(xhi, xlo, wkvh, wkvl, kv, NROW, CC, CC);

    // (6-8) RoPE + split + head-major relayout
    {
        int totq = NROW * HH * 64;
        rope_split_kernel<<<(totq + 255) / 256, 256>>>(q, qh, ql, HH, CC, totq);
        int totk = NROW * HKV * 64;
        rope_split_kernel<<<(totk + 255) / 256, 256>>>(kv, kh, kl, HKV, CC, totk);
        int totv = NROW * HKV * 32;
        v_split_kernel<<<(totv + 255) / 256, 256>>>(kv + HKV*DD, vh, vl, CC, totv);
    }

    // (9) attention
    attn_mma_kernel<<<dim3(TT / ABQ, HH, BB), 256, ASM_BYTES>>>(qh, ql, kh, kl, vh, vl, ohi, olo);

    // (10) transpose + split Wp (deferred)
    transpose_split_kernel<<<dim3(CC/32, CC/32), dim3(32, 8)>>>(Wp, wph, wpl, CC, CC);

    // (11) output projection
    gemm_mma_kernel<<<dim3(CC/GBN, NROW/GBM), GEMM_THREADS, GEMM_SMEM>>>(ohi, olo, wph, wpl, out, NROW, CC, CC);
}